// round 5
// baseline (speedup 1.0000x reference)
#include <cuda_runtime.h>
#include <cstdint>

// SAGE_68281390072709 — 2-layer GraphSAGE, fp32.
// Dual-output tf32 tensor-core GEMMs (cp.async double-buffered) + CSR gather.

#define NN 50000
#define EE 800000
#define F0 128
#define F1 128
#define NC 41

__device__ float g_Y0[NN * F1];
__device__ float g_h[NN * F1];
__device__ float g_Y1[NN * NC];
__device__ int   g_deg[NN];
__device__ int   g_rowptr[NN + 1];
__device__ int   g_cursor[NN];
__device__ int   g_csr_src[EE];
__device__ float g_W1s[F1 * 64];   // W_self1 zero-padded to [128,64]
__device__ float g_W1n[F1 * 64];   // W_neigh1 zero-padded to [128,64]

// ---------------------------------------------------------------------------
// CSR construction
// ---------------------------------------------------------------------------
__global__ void zero_deg_kernel() {
    int i = blockIdx.x * blockDim.x + threadIdx.x;
    if (i < NN) g_deg[i] = 0;
}

__global__ void hist_kernel(const int* __restrict__ dst, int E) {
    int i = blockIdx.x * blockDim.x + threadIdx.x;
    if (i < E) atomicAdd(&g_deg[dst[i]], 1);
}

// single-kernel exclusive scan of g_deg -> g_rowptr / g_cursor
__global__ void __launch_bounds__(1024)
scan_fused_kernel() {
    __shared__ int s[1024];
    const int PER = 49;          // 1024*49 = 50176 >= NN
    int t = threadIdx.x;
    int base = t * PER;
    int sum = 0;
    for (int j = 0; j < PER; j++) {
        int i = base + j;
        if (i < NN) sum += g_deg[i];
    }
    s[t] = sum;
    __syncthreads();
#pragma unroll
    for (int off = 1; off < 1024; off <<= 1) {
        int v = (t >= off) ? s[t - off] : 0;
        __syncthreads();
        s[t] += v;
        __syncthreads();
    }
    int run = s[t] - sum;        // exclusive prefix for this thread's chunk
    for (int j = 0; j < PER; j++) {
        int i = base + j;
        if (i < NN) {
            g_rowptr[i] = run;
            g_cursor[i] = run;
            run += g_deg[i];
        }
    }
    if (t == 1023) g_rowptr[NN] = s[1023];
}

__global__ void fill_kernel(const int* __restrict__ src,
                            const int* __restrict__ dst, int E) {
    int e = blockIdx.x * blockDim.x + threadIdx.x;
    if (e < E) {
        int pos = atomicAdd(&g_cursor[dst[e]], 1);
        g_csr_src[pos] = src[e];
    }
}

// zero-pad layer-1 weights [128,41] -> [128,64]
__global__ void pad_w1_kernel(const float* __restrict__ Ws,
                              const float* __restrict__ Wn) {
    int i = blockIdx.x * blockDim.x + threadIdx.x;
    if (i >= F1 * 64) return;
    int r = i >> 6, c = i & 63;
    float vs = (c < NC) ? Ws[r * NC + c] : 0.f;
    float vn = (c < NC) ? Wn[r * NC + c] : 0.f;
    g_W1s[i] = vs;
    g_W1n[i] = vn;
}

// ---------------------------------------------------------------------------
// tf32 helpers
// ---------------------------------------------------------------------------
__device__ __forceinline__ uint32_t f2tf32(float x) {
    uint32_t r;
    asm("cvt.rna.tf32.f32 %0, %1;" : "=r"(r) : "f"(x));
    return r;
}

__device__ __forceinline__ void mma_tf32(float* c, const uint32_t* a, const uint32_t* b) {
    asm volatile(
        "mma.sync.aligned.m16n8k8.row.col.f32.tf32.tf32.f32 "
        "{%0,%1,%2,%3}, {%4,%5,%6,%7}, {%8,%9}, {%0,%1,%2,%3};"
        : "+f"(c[0]), "+f"(c[1]), "+f"(c[2]), "+f"(c[3])
        : "r"(a[0]), "r"(a[1]), "r"(a[2]), "r"(a[3]), "r"(b[0]), "r"(b[1]));
}

__device__ __forceinline__ void cp_async16(void* sdst, const void* gsrc, bool valid) {
    uint32_t s = (uint32_t)__cvta_generic_to_shared(sdst);
    int sz = valid ? 16 : 0;
    asm volatile("cp.async.cg.shared.global [%0], [%1], 16, %2;"
                 :: "r"(s), "l"(gsrc), "r"(sz));
}
#define CP_COMMIT() asm volatile("cp.async.commit_group;")

// ---------------------------------------------------------------------------
// dual-output tf32 GEMM: Cs = A@Bs, Cn = A@Bn.  A:[M,K] fp32, B:[K,ldb] fp32.
// BM=128, BN=64, BK=16, 256 threads (8 warps), warp tile 32x32, double-buffered.
// GUARD_STORE: guard C columns against N (layer-1, N=41).
// ---------------------------------------------------------------------------
template <bool GUARD_STORE>
__global__ void __launch_bounds__(256, 1)
dual_gemm_kernel(const float* __restrict__ A,
                 const float* __restrict__ Bs_g,
                 const float* __restrict__ Bn_g,
                 float* __restrict__ Cs,
                 float* __restrict__ Cn,
                 int M, int N, int K, int ldb) {
    constexpr int BM = 128, BN = 64, BK = 16;
    __shared__ float As[2][BM][BK + 4];
    __shared__ float Bs[2][2][BK][BN + 8];

    const int tid = threadIdx.x;
    const int lane = tid & 31;
    const int wid = tid >> 5;
    const int g = lane >> 2;
    const int t = lane & 3;
    const int wm = (wid >> 1) * 32;
    const int wn = (wid & 1) * 32;
    const int m0 = blockIdx.x * BM;
    const int n0 = blockIdx.y * BN;

    const int b_row = tid >> 4;            // 0..15
    const int b_c4 = (tid & 15) * 4;       // 0..60

    float acc[2][2][4][4];                 // [mat][mf][nf][i]
#pragma unroll
    for (int m = 0; m < 2; m++)
#pragma unroll
        for (int mf = 0; mf < 2; mf++)
#pragma unroll
            for (int nf = 0; nf < 4; nf++)
#pragma unroll
                for (int i = 0; i < 4; i++) acc[m][mf][nf][i] = 0.f;

    const int KT = K / BK;

    auto load_tile = [&](int kt, int buf) {
        int k0 = kt * BK;
#pragma unroll
        for (int i = 0; i < 2; i++) {
            int v = tid + i * 256;         // 0..511
            int row = v >> 2;              // 0..127
            int c4 = (v & 3) * 4;          // 0,4,8,12
            int gm = m0 + row;
            cp_async16(&As[buf][row][c4], A + (long)gm * K + k0 + c4, gm < M);
        }
        cp_async16(&Bs[buf][0][b_row][b_c4], Bs_g + (long)(k0 + b_row) * ldb + n0 + b_c4, true);
        cp_async16(&Bs[buf][1][b_row][b_c4], Bn_g + (long)(k0 + b_row) * ldb + n0 + b_c4, true);
    };

    load_tile(0, 0);
    CP_COMMIT();

    for (int kt = 0; kt < KT; kt++) {
        int cur = kt & 1;
        if (kt + 1 < KT) {
            load_tile(kt + 1, cur ^ 1);
            CP_COMMIT();
            asm volatile("cp.async.wait_group 1;");
        } else {
            asm volatile("cp.async.wait_group 0;");
        }
        __syncthreads();

#pragma unroll
        for (int ks = 0; ks < BK; ks += 8) {
            uint32_t a[2][4];
#pragma unroll
            for (int mf = 0; mf < 2; mf++) {
                int r = wm + mf * 16;
                a[mf][0] = f2tf32(As[cur][r + g][ks + t]);
                a[mf][1] = f2tf32(As[cur][r + g + 8][ks + t]);
                a[mf][2] = f2tf32(As[cur][r + g][ks + t + 4]);
                a[mf][3] = f2tf32(As[cur][r + g + 8][ks + t + 4]);
            }
#pragma unroll
            for (int m = 0; m < 2; m++) {
#pragma unroll
                for (int nf = 0; nf < 4; nf++) {
                    int c = wn + nf * 8 + g;
                    uint32_t b[2];
                    b[0] = f2tf32(Bs[cur][m][ks + t][c]);
                    b[1] = f2tf32(Bs[cur][m][ks + t + 4][c]);
#pragma unroll
                    for (int mf = 0; mf < 2; mf++)
                        mma_tf32(acc[m][mf][nf], a[mf], b);
                }
            }
        }
        __syncthreads();
    }

    // store both outputs
#pragma unroll
    for (int m = 0; m < 2; m++) {
        float* Cp = m ? Cn : Cs;
#pragma unroll
        for (int mf = 0; mf < 2; mf++) {
#pragma unroll
            for (int nf = 0; nf < 4; nf++) {
                int row0 = m0 + wm + mf * 16 + g;
                int col0 = n0 + wn + nf * 8 + 2 * t;
#pragma unroll
                for (int rr = 0; rr < 2; rr++) {
                    int row = row0 + rr * 8;
                    if (row >= M) continue;
                    float* cp = Cp + (long)row * N + col0;
                    if (!GUARD_STORE || col0 < N)     cp[0] = acc[m][mf][nf][rr * 2 + 0];
                    if (!GUARD_STORE || col0 + 1 < N) cp[1] = acc[m][mf][nf][rr * 2 + 1];
                }
            }
        }
    }
}

// ---------------------------------------------------------------------------
// layer-0 gather + finalize: warp per node.
// ---------------------------------------------------------------------------
__global__ void __launch_bounds__(256)
gather0_kernel(const float* __restrict__ b0) {
    int warp = (blockIdx.x * blockDim.x + threadIdx.x) >> 5;
    if (warp >= NN) return;
    int lane = threadIdx.x & 31;
    int beg = g_rowptr[warp];
    int end = g_rowptr[warp + 1];

    float4 acc = make_float4(0.f, 0.f, 0.f, 0.f);
    int e = beg;
    for (; e + 1 < end; e += 2) {
        int s0 = g_csr_src[e];
        int s1 = g_csr_src[e + 1];
        float4 v0 = *reinterpret_cast<const float4*>(g_Y0 + (long)s0 * F1 + lane * 4);
        float4 v1 = *reinterpret_cast<const float4*>(g_Y0 + (long)s1 * F1 + lane * 4);
        acc.x += v0.x + v1.x;
        acc.y += v0.y + v1.y;
        acc.z += v0.z + v1.z;
        acc.w += v0.w + v1.w;
    }
    if (e < end) {
        int s0 = g_csr_src[e];
        float4 v0 = *reinterpret_cast<const float4*>(g_Y0 + (long)s0 * F1 + lane * 4);
        acc.x += v0.x; acc.y += v0.y; acc.z += v0.z; acc.w += v0.w;
    }

    float invd = 1.0f / fmaxf((float)(end - beg), 1.0f);
    float4 h = *reinterpret_cast<const float4*>(g_h + (long)warp * F1 + lane * 4);
    float4 b = *reinterpret_cast<const float4*>(b0 + lane * 4);
    h.x = fmaxf(h.x + acc.x * invd + b.x, 0.f);
    h.y = fmaxf(h.y + acc.y * invd + b.y, 0.f);
    h.z = fmaxf(h.z + acc.z * invd + b.z, 0.f);
    h.w = fmaxf(h.w + acc.w * invd + b.w, 0.f);
    *reinterpret_cast<float4*>(g_h + (long)warp * F1 + lane * 4) = h;
}

// ---------------------------------------------------------------------------
// layer-1 gather + finalize: warp per node, 41 features.
// ---------------------------------------------------------------------------
__global__ void __launch_bounds__(256)
gather1_kernel(float* __restrict__ out, const float* __restrict__ b1) {
    int warp = (blockIdx.x * blockDim.x + threadIdx.x) >> 5;
    if (warp >= NN) return;
    int lane = threadIdx.x & 31;
    int beg = g_rowptr[warp];
    int end = g_rowptr[warp + 1];
    bool hi = (lane < NC - 32);

    float acc0 = 0.f, acc1 = 0.f;
    int e = beg;
    for (; e + 1 < end; e += 2) {
        int s0 = g_csr_src[e];
        int s1 = g_csr_src[e + 1];
        const float* r0 = g_Y1 + (long)s0 * NC;
        const float* r1 = g_Y1 + (long)s1 * NC;
        acc0 += r0[lane] + r1[lane];
        if (hi) acc1 += r0[lane + 32] + r1[lane + 32];
    }
    if (e < end) {
        const float* r0 = g_Y1 + (long)g_csr_src[e] * NC;
        acc0 += r0[lane];
        if (hi) acc1 += r0[lane + 32];
    }

    float invd = 1.0f / fmaxf((float)(end - beg), 1.0f);
    float* o = out + (long)warp * NC;
    o[lane] = o[lane] + acc0 * invd + b1[lane];
    if (hi) o[lane + 32] = o[lane + 32] + acc1 * invd + b1[lane + 32];
}

// ---------------------------------------------------------------------------
extern "C" void kernel_launch(void* const* d_in, const int* in_sizes, int n_in,
                              void* d_out, int out_size) {
    const float* x        = (const float*)d_in[0];
    const int*   src      = (const int*)d_in[1];
    const int*   dst      = (const int*)d_in[2];
    const float* W_self0  = (const float*)d_in[3];
    const float* W_neigh0 = (const float*)d_in[4];
    const float* b0       = (const float*)d_in[5];
    const float* W_self1  = (const float*)d_in[6];
    const float* W_neigh1 = (const float*)d_in[7];
    const float* b1       = (const float*)d_in[8];
    float* out = (float*)d_out;

    const int M = in_sizes[0] / F0;   // 50000
    const int E = in_sizes[1];        // 800000

    float* dY0; cudaGetSymbolAddress((void**)&dY0, g_Y0);
    float* dY1; cudaGetSymbolAddress((void**)&dY1, g_Y1);
    float* dH;  cudaGetSymbolAddress((void**)&dH,  g_h);
    float* dW1s; cudaGetSymbolAddress((void**)&dW1s, g_W1s);
    float* dW1n; cudaGetSymbolAddress((void**)&dW1n, g_W1n);

    // --- CSR build + weight padding ---
    zero_deg_kernel<<<(NN + 255) / 256, 256>>>();
    hist_kernel<<<(E + 255) / 256, 256>>>(dst, E);
    scan_fused_kernel<<<1, 1024>>>();
    fill_kernel<<<(E + 255) / 256, 256>>>(src, dst, E);
    pad_w1_kernel<<<(F1 * 64 + 255) / 256, 256>>>(W_self1, W_neigh1);

    // --- layer 0: S0->g_h, Y0->g_Y0 in one dual GEMM ---
    dim3 thr(256);
    dim3 g0((M + 127) / 128, F1 / 64);   // (391, 2)
    dual_gemm_kernel<false><<<g0, thr>>>(x, W_self0, W_neigh0, dH, dY0,
                                         M, F1, F0, F1);

    // --- layer-0 gather + finalize (relu fused) ---
    gather0_kernel<<<(NN * 32 + 255) / 256, 256>>>(b0);

    // --- layer 1: S1->out, Y1->g_Y1 in one dual GEMM (padded weights) ---
    dim3 g1((M + 127) / 128, 1);
    dual_gemm_kernel<true><<<g1, thr>>>(dH, dW1s, dW1n, out, dY1,
                                        M, NC, F1, 64);

    // --- layer-1 gather + finalize ---
    gather1_kernel<<<(NN * 32 + 255) / 256, 256>>>(out, b1);
}